// round 12
// baseline (speedup 1.0000x reference)
#include <cuda_runtime.h>
#include <cstdint>

#define Bq 2
#define Hq 8
#define Sq 2048
#define Dq 64
#define TEMP 8.0f

#define BM 128
#define BN 64
#define NT 512
#define NTILES (Sq / BN)   // 32

// smem word offsets
#define W_Q   0                      // q tf32 [128][68]
#define W_K0  8704                   // k raw f32 [64][68] natural [t][d], buf 0
#define W_K1  13056                  // buf 1
#define W_VR0 17408                  // v raw f32 [64][68], buf 0
#define W_VR1 21760                  // buf 1
#define W_VH  26112                  // v^T hi bf16x2 [64][36] ([d][tpair])
#define W_VL  28416                  // v^T lo bf16x2 [64][36]
#define W_EH  30720                  // e hi bf16x2 [128][36] ([row][tpair])
#define W_EL  35328                  // e lo bf16x2 [128][36]
#define W_RS  39936                  // rowsum [4][128] floats
#define SMEM_WORDS 40448
#define SMEM_BYTES (SMEM_WORDS * 4)  // 161792 B -> 1 CTA/SM

#define KVS 68     // K / Vraw row stride (words)
#define EVS 36     // row stride (words) for VH/VL/EH/EL

// masked-cov scratch: covm = mask ? cov : -3e4   (33.5 MB)
__device__ float g_covm[(size_t)Bq * Sq * Sq];
// per-row softmax denominators
__device__ float g_rowsum[(size_t)Bq * Hq * Sq];

static __device__ __forceinline__ uint32_t f2tf32(float f) {
    uint32_t r;
    asm("cvt.rna.tf32.f32 %0, %1;" : "=r"(r) : "f"(f));
    return r;
}
static __device__ __forceinline__ uint32_t bf16x2(float hi, float lo) {
    uint32_t r;
    asm("cvt.rn.bf16x2.f32 %0, %1, %2;" : "=r"(r) : "f"(hi), "f"(lo));
    return r;
}
// exp(x) on fma/alu pipes only (no MUFU). Caller clamps x >= -60.
static __device__ __forceinline__ float fexp(float x) {
    const float L2E = 1.4426950408889634f;
    float t = fmaf(x, L2E, 12582912.0f);          // 1.5*2^23: rounds to int
    int   in = __float_as_int(t);
    float n  = t - 12582912.0f;
    float z  = fmaf(x, L2E, -n);                  // frac in [-0.5, 0.5]
    float w  = z * 0.6931471805599453f;
    float p  = fmaf(w, 8.3333333e-3f, 4.1666667e-2f);
    p = fmaf(p, w, 0.16666667f);
    p = fmaf(p, w, 0.5f);
    p = fmaf(p, w, 1.0f);
    p = fmaf(p, w, 1.0f);
    return __int_as_float(__float_as_int(p) + (in << 23));
}
static __device__ __forceinline__ void mma_tf32(float* d, const uint32_t* a,
                                                const uint32_t* b) {
    asm volatile(
        "mma.sync.aligned.m16n8k8.row.col.f32.tf32.tf32.f32 "
        "{%0,%1,%2,%3}, {%4,%5,%6,%7}, {%8,%9}, {%0,%1,%2,%3};"
        : "+f"(d[0]), "+f"(d[1]), "+f"(d[2]), "+f"(d[3])
        : "r"(a[0]), "r"(a[1]), "r"(a[2]), "r"(a[3]), "r"(b[0]), "r"(b[1]));
}
static __device__ __forceinline__ void mma_bf16(float* d, const uint32_t* a,
                                                const uint32_t* b) {
    asm volatile(
        "mma.sync.aligned.m16n8k16.row.col.f32.bf16.bf16.f32 "
        "{%0,%1,%2,%3}, {%4,%5,%6,%7}, {%8,%9}, {%0,%1,%2,%3};"
        : "+f"(d[0]), "+f"(d[1]), "+f"(d[2]), "+f"(d[3])
        : "r"(a[0]), "r"(a[1]), "r"(a[2]), "r"(a[3]), "r"(b[0]), "r"(b[1]));
}
static __device__ __forceinline__ void cp16(uint32_t dst, const void* src) {
    asm volatile("cp.async.cg.shared.global [%0], [%1], 16;"
                 :: "r"(dst), "l"(src) : "memory");
}

// Pre-kernel: fold mask into cov (one streaming pass, high occupancy)
__global__ __launch_bounds__(256, 8)
void covmask_kernel(const float* __restrict__ cov, const int* __restrict__ mask)
{
    size_t i = ((size_t)blockIdx.x * 256 + threadIdx.x) * 4;
    float4 c = *(const float4*)(cov + i);
    int4   m = *(const int4*)(mask + i);
    float4 o;
    o.x = m.x ? c.x : -30000.0f;
    o.y = m.y ? c.y : -30000.0f;
    o.z = m.z ? c.z : -30000.0f;
    o.w = m.w ? c.w : -30000.0f;
    *(float4*)(g_covm + i) = o;
}

// Post-kernel: scale each attn row by 1/rowsum (high-occupancy streaming)
__global__ __launch_bounds__(256, 8)
void attn_normalize_kernel(float* __restrict__ attn)
{
    size_t i = (size_t)blockIdx.x * 256 + threadIdx.x;  // float4 index
    size_t row = (i * 4) >> 11;                         // element / 2048
    float inv = 1.0f / g_rowsum[row];
    float4 a = ((float4*)attn)[i];
    a.x *= inv; a.y *= inv; a.z *= inv; a.w *= inv;
    ((float4*)attn)[i] = a;
}

__global__ __launch_bounds__(NT, 1)
void attn_mma_kernel(const float* __restrict__ q,
                     const float* __restrict__ k,
                     const float* __restrict__ v,
                     const float* __restrict__ lambda_w,
                     float* __restrict__ out,      // [B,H,S,D]
                     float* __restrict__ attn)     // [B,H,S,S]
{
    extern __shared__ uint32_t sw[];
    const uint32_t sbase = (uint32_t)__cvta_generic_to_shared(sw);
    uint32_t* QW  = sw + W_Q;
    uint32_t* VHW = sw + W_VH;
    uint32_t* VLW = sw + W_VL;
    uint32_t* EHW = sw + W_EH;
    uint32_t* ELW = sw + W_EL;
    float*    rs  = (float*)(sw + W_RS);

    const int h     = blockIdx.x;   // innermost -> heads share covm in L2
    const int mpair = blockIdx.y;   // 2 mtiles per CTA
    const int b     = blockIdx.z;
    const int bh    = b * Hq + h;
    const int tid   = threadIdx.x;
    const int wid   = tid >> 5;
    const int lane  = tid & 31;
    const int lg    = lane >> 2;    // group 0..7
    const int lt    = lane & 3;     // 0..3

    const int warp_m = wid & 3;     // row group (32 rows)
    const int warp_n = wid >> 2;    // 0..3: 16-col / 16-d slice
    const int rm = warp_m * 32;
    const int cn = warp_n * 16;
    const int dn = warp_n * 16;

    const float lam  = lambda_w[h];
    const float wcov = lam / (lam + 1.0f);
    const float sqk  = 1.0f / ((lam + 1.0f) * TEMP);

    const float* kg = k + (size_t)bh * Sq * Dq;
    const float* vg = v + (size_t)bh * Sq * Dq;

    for (int m = 0; m < 2; m++) {
        const int mtile = mpair * 2 + m;
        const float* qg    = q + ((size_t)bh * Sq + (size_t)mtile * BM) * Dq;
        const float* covg  = g_covm + ((size_t)b * Sq + (size_t)mtile * BM) * Sq;
        float*       attng = attn + ((size_t)bh * Sq + (size_t)mtile * BM) * Sq;
        float*       outg  = out  + ((size_t)bh * Sq + (size_t)mtile * BM) * Dq;

        // ---- prefetch tile 0 (K + Vraw) ----
        {
#pragma unroll
            for (int it = 0; it < 2; it++) {
                int idx = tid + it * NT;   // 1024 16B segs each
                int t   = idx >> 4;
                int seg = idx & 15;
                cp16(sbase + (uint32_t)(W_K0  + t * KVS + seg * 4) * 4,
                     kg + (size_t)t * Dq + seg * 4);
                cp16(sbase + (uint32_t)(W_VR0 + t * KVS + seg * 4) * 4,
                     vg + (size_t)t * Dq + seg * 4);
            }
            asm volatile("cp.async.commit_group;" ::: "memory");
        }

        __syncthreads();   // QW free (previous mtile done reading)
        // ---- fill q smem (tf32) ----
#pragma unroll
        for (int it = 0; it < 4; it++) {
            int idx = tid + it * NT;        // 2048 float4
            int r  = idx >> 4;
            int c4 = (idx & 15) << 2;
            float4 f = *(const float4*)&qg[r * Dq + c4];
            uint4 o;
            o.x = f2tf32(f.x); o.y = f2tf32(f.y);
            o.z = f2tf32(f.z); o.w = f2tf32(f.w);
            *(uint4*)&QW[r * 68 + c4] = o;
        }

        float oacc[2][2][4];
#pragma unroll
        for (int mi = 0; mi < 2; mi++)
#pragma unroll
            for (int nf = 0; nf < 2; nf++)
#pragma unroll
                for (int c = 0; c < 4; c++) oacc[mi][nf][c] = 0.0f;
        float rowsum[4] = {0.0f, 0.0f, 0.0f, 0.0f};

        for (int nt = 0; nt < NTILES; nt++) {
            const int buf = nt & 1;
            const int kof = buf ? W_K1 : W_K0;
            const int vof = buf ? W_VR1 : W_VR0;
            const int t0  = nt * BN;

            // ---- prefetch next tile, then wait for current ----
            if (nt + 1 < NTILES) {
                const int kofn = buf ? W_K0 : W_K1;
                const int vofn = buf ? W_VR0 : W_VR1;
                const float* kn = kg + (size_t)(t0 + BN) * Dq;
                const float* vn = vg + (size_t)(t0 + BN) * Dq;
#pragma unroll
                for (int it = 0; it < 2; it++) {
                    int idx = tid + it * NT;
                    int t   = idx >> 4;
                    int seg = idx & 15;
                    cp16(sbase + (uint32_t)(kofn + t * KVS + seg * 4) * 4,
                         kn + (size_t)t * Dq + seg * 4);
                    cp16(sbase + (uint32_t)(vofn + t * KVS + seg * 4) * 4,
                         vn + (size_t)t * Dq + seg * 4);
                }
                asm volatile("cp.async.commit_group;" ::: "memory");
                asm volatile("cp.async.wait_group 1;" ::: "memory");
            } else {
                asm volatile("cp.async.wait_group 0;" ::: "memory");
            }
            __syncthreads();   // cp data visible; prev AV done with VH/VL/E

            // ---- convert Vraw -> split-bf16 VH/VL (1 item/thread) ----
            {
                const uint32_t* VR = sw + vof;
                int tp = tid & 31;
                int d4 = (tid >> 5) << 2;
                float4 v0 = *(const float4*)&VR[(2 * tp)     * KVS + d4];
                float4 v1 = *(const float4*)&VR[(2 * tp + 1) * KVS + d4];
                const float e0[4] = {v0.x, v0.y, v0.z, v0.w};
                const float e1[4] = {v1.x, v1.y, v1.z, v1.w};
#pragma unroll
                for (int i = 0; i < 4; i++) {
                    uint32_t hp = bf16x2(e1[i], e0[i]);
                    float f0 = __uint_as_float(hp << 16);
                    float f1 = __uint_as_float(hp & 0xffff0000u);
                    uint32_t lp = bf16x2(e1[i] - f1, e0[i] - f0);
                    VHW[(d4 + i) * EVS + tp] = hp;
                    VLW[(d4 + i) * EVS + tp] = lp;
                }
            }
            __syncthreads();

            // ---- cov prefetch (hidden behind QK MMA) ----
            float2 cv[2][2][2];
#pragma unroll
            for (int mi = 0; mi < 2; mi++)
#pragma unroll
                for (int rh = 0; rh < 2; rh++) {
                    const int r = rm + mi * 16 + lg + rh * 8;
#pragma unroll
                    for (int ni = 0; ni < 2; ni++)
                        cv[mi][rh][ni] = *(const float2*)
                            (covg + (size_t)r * Sq + t0 + cn + ni * 8 + 2 * lt);
                }

            // ---- scores: warp tile 32 rows x 16 cols, tf32 mma ----
            const uint32_t* KB = sw + kof;   // natural [t][d], raw f32 as tf32
            float acc[2][2][4];
#pragma unroll
            for (int mi = 0; mi < 2; mi++)
#pragma unroll
                for (int ni = 0; ni < 2; ni++)
#pragma unroll
                    for (int c = 0; c < 4; c++) acc[mi][ni][c] = 0.0f;

#pragma unroll
            for (int ks = 0; ks < 8; ks++) {
                const int kd = ks * 8;
                uint32_t a[2][4], bb[2][2];
#pragma unroll
                for (int mi = 0; mi < 2; mi++) {
                    const uint32_t* q0 = QW + (rm + mi * 16 + lg) * 68 + kd + lt;
                    a[mi][0] = q0[0];
                    a[mi][1] = q0[8 * 68];
                    a[mi][2] = q0[4];
                    a[mi][3] = q0[8 * 68 + 4];
                }
#pragma unroll
                for (int ni = 0; ni < 2; ni++) {
                    const uint32_t* kp = KB + (cn + ni * 8 + lg) * KVS + kd + lt;
                    bb[ni][0] = kp[0];
                    bb[ni][1] = kp[4];
                }
#pragma unroll
                for (int mi = 0; mi < 2; mi++)
#pragma unroll
                    for (int ni = 0; ni < 2; ni++)
                        mma_tf32(acc[mi][ni], a[mi], bb[ni]);
            }

            // ---- epilogue: blend, exp, attn store, pack e ----
#pragma unroll
            for (int mi = 0; mi < 2; mi++) {
#pragma unroll
                for (int rh = 0; rh < 2; rh++) {
                    const int r = rm + mi * 16 + lg + rh * 8;
                    float* ar = attng + (size_t)r * Sq + t0;
                    uint32_t* ehr = EHW + r * EVS;
                    uint32_t* elr = ELW + r * EVS;
                    float rsacc = 0.0f;
#pragma unroll
                    for (int ni = 0; ni < 2; ni++) {
                        const int c = cn + ni * 8 + 2 * lt;
                        float s0 = acc[mi][ni][rh * 2 + 0];
                        float s1 = acc[mi][ni][rh * 2 + 1];
                        float l0 = fmaxf(fmaf(sqk, s0, wcov * cv[mi][rh][ni].x), -60.0f);
                        float l1 = fmaxf(fmaf(sqk, s1, wcov * cv[mi][rh][ni].y), -60.0f);
                        float e0 = fexp(l0);
                        float e1 = fexp(l1);
                        rsacc += e0 + e1;
                        *(float2*)(ar + c) = make_float2(e0, e1);
                        uint32_t hp = bf16x2(e1, e0);
                        float f0 = __uint_as_float(hp << 16);
                        float f1 = __uint_as_float(hp & 0xffff0000u);
                        uint32_t lp = bf16x2(e1 - f1, e0 - f0);
                        const int tpl = c >> 1;
                        ehr[tpl] = hp;
                        elr[tpl] = lp;
                    }
                    rowsum[mi * 2 + rh] += rsacc;
                }
            }
            __syncthreads();

            // ---- AV: warp tile 32 rows x 16 d, k=64 via 4 k16 steps ----
#pragma unroll
            for (int ks = 0; ks < 4; ks++) {
                const int tpb = ks * 8 + lt;
                uint32_t ah[2][4], al[2][4], bh[2][2], bl[2][2];
#pragma unroll
                for (int mi = 0; mi < 2; mi++) {
                    const int base = (rm + mi * 16 + lg) * EVS + tpb;
                    ah[mi][0] = EHW[base];
                    ah[mi][1] = EHW[base + 8 * EVS];
                    ah[mi][2] = EHW[base + 4];
                    ah[mi][3] = EHW[base + 8 * EVS + 4];
                    al[mi][0] = ELW[base];
                    al[mi][1] = ELW[base + 8 * EVS];
                    al[mi][2] = ELW[base + 4];
                    al[mi][3] = ELW[base + 8 * EVS + 4];
                }
#pragma unroll
                for (int nf = 0; nf < 2; nf++) {
                    const int base = (dn + nf * 8 + lg) * EVS + tpb;
                    bh[nf][0] = VHW[base];
                    bh[nf][1] = VHW[base + 4];
                    bl[nf][0] = VLW[base];
                    bl[nf][1] = VLW[base + 4];
                }
#pragma unroll
                for (int mi = 0; mi < 2; mi++)
#pragma unroll
                    for (int nf = 0; nf < 2; nf++) {
                        mma_bf16(oacc[mi][nf], ah[mi], bh[nf]);
                        mma_bf16(oacc[mi][nf], ah[mi], bl[nf]);
                        mma_bf16(oacc[mi][nf], al[mi], bh[nf]);
                    }
            }
        }

        // ---- rowsum: reduce over lane&3, store partials ----
#pragma unroll
        for (int i = 0; i < 4; i++) {
            rowsum[i] += __shfl_xor_sync(0xffffffffu, rowsum[i], 1);
            rowsum[i] += __shfl_xor_sync(0xffffffffu, rowsum[i], 2);
        }
        if (lt == 0) {
#pragma unroll
            for (int mi = 0; mi < 2; mi++)
#pragma unroll
                for (int rh = 0; rh < 2; rh++)
                    rs[warp_n * 128 + rm + mi * 16 + lg + rh * 8] = rowsum[mi * 2 + rh];
        }
        __syncthreads();

        // ---- publish rowsums for the normalize pass ----
        if (tid < 128)
            g_rowsum[(size_t)bh * Sq + (size_t)mtile * BM + tid] =
                rs[tid] + rs[128 + tid] + rs[256 + tid] + rs[384 + tid];

        // ---- write normalized output ----
#pragma unroll
        for (int mi = 0; mi < 2; mi++) {
#pragma unroll
            for (int rh = 0; rh < 2; rh++) {
                const int r = rm + mi * 16 + lg + rh * 8;
                const float iv = 1.0f /
                    (rs[r] + rs[128 + r] + rs[256 + r] + rs[384 + r]);
#pragma unroll
                for (int nf = 0; nf < 2; nf++) {
                    const int d = dn + nf * 8 + 2 * lt;
                    float2 o;
                    o.x = oacc[mi][nf][rh * 2 + 0] * iv;
                    o.y = oacc[mi][nf][rh * 2 + 1] * iv;
                    *(float2*)(outg + (size_t)r * Dq + d) = o;
                }
            }
        }
    }
}

extern "C" void kernel_launch(void* const* d_in, const int* in_sizes, int n_in,
                              void* d_out, int out_size)
{
    const float* q    = (const float*)d_in[0];
    const float* k    = (const float*)d_in[1];
    const float* v    = (const float*)d_in[2];
    const float* cov  = (const float*)d_in[3];
    const float* lam  = (const float*)d_in[4];
    const int*   mask = (const int*)d_in[5];

    float* out  = (float*)d_out;                          // [B,H,S,D]
    float* attn = out + (size_t)Bq * Hq * Sq * Dq;        // [B,H,S,S]

    // pass 0: fold mask into cov (streaming)
    const size_t n4 = (size_t)Bq * Sq * Sq / 4;
    covmask_kernel<<<(unsigned)(n4 / 256), 256>>>(cov, mask);

    cudaFuncSetAttribute(attn_mma_kernel,
                         cudaFuncAttributeMaxDynamicSharedMemorySize, SMEM_BYTES);
    dim3 grid(Hq, Sq / BM / 2, Bq);  // (8, 8, 2) = 128 CTAs, single wave
    attn_mma_kernel<<<grid, NT, SMEM_BYTES>>>(q, k, v, lam, out, attn);

    // pass 2: normalize attn at streaming occupancy (R1-measured 5.1 TB/s)
    const size_t total4 = (size_t)Bq * Hq * Sq * Sq / 4;  // 16,777,216
    attn_normalize_kernel<<<(unsigned)(total4 / 256), 256>>>(attn);
}

// round 13
// speedup vs baseline: 1.0601x; 1.0601x over previous
#include <cuda_runtime.h>
#include <cstdint>

#define Bq 2
#define Hq 8
#define Sq 2048
#define Dq 64
#define TEMP 8.0f

#define BM 128
#define BN 64
#define NT 512
#define NTILES (Sq / BN)   // 32

// smem word offsets
#define W_Q   0                      // q tf32 [128][68]
#define W_K0  8704                   // k raw f32 [64][68] natural [t][d], buf 0
#define W_K1  13056                  // buf 1
#define W_VR0 17408                  // v raw f32 [64][68] natural [t][d], buf 0
#define W_VR1 21760                  // buf 1
#define W_E   26112                  // e exact f32 [128][76] ([row][t])
#define W_RS  35840                  // rowsum [4][128] floats
#define SMEM_WORDS 36352
#define SMEM_BYTES (SMEM_WORDS * 4)  // 145408 B

#define KVS 68     // K / Vraw row stride (words)
#define ES  76     // E row stride (words)

// masked-cov scratch: covm = mask ? cov : -3e4   (33.5 MB)
__device__ float g_covm[(size_t)Bq * Sq * Sq];

static __device__ __forceinline__ uint32_t f2tf32(float f) {
    uint32_t r;
    asm("cvt.rna.tf32.f32 %0, %1;" : "=r"(r) : "f"(f));
    return r;
}
// exp(x) on fma/alu pipes only (no MUFU). Caller clamps x >= -60.
static __device__ __forceinline__ float fexp(float x) {
    const float L2E = 1.4426950408889634f;
    float t = fmaf(x, L2E, 12582912.0f);          // 1.5*2^23: rounds to int
    int   in = __float_as_int(t);
    float n  = t - 12582912.0f;
    float z  = fmaf(x, L2E, -n);                  // frac in [-0.5, 0.5]
    float w  = z * 0.6931471805599453f;
    float p  = fmaf(w, 8.3333333e-3f, 4.1666667e-2f);
    p = fmaf(p, w, 0.16666667f);
    p = fmaf(p, w, 0.5f);
    p = fmaf(p, w, 1.0f);
    p = fmaf(p, w, 1.0f);
    return __int_as_float(__float_as_int(p) + (in << 23));
}
static __device__ __forceinline__ void mma_tf32(float* d, const uint32_t* a,
                                                const uint32_t* b) {
    asm volatile(
        "mma.sync.aligned.m16n8k8.row.col.f32.tf32.tf32.f32 "
        "{%0,%1,%2,%3}, {%4,%5,%6,%7}, {%8,%9}, {%0,%1,%2,%3};"
        : "+f"(d[0]), "+f"(d[1]), "+f"(d[2]), "+f"(d[3])
        : "r"(a[0]), "r"(a[1]), "r"(a[2]), "r"(a[3]), "r"(b[0]), "r"(b[1]));
}
static __device__ __forceinline__ void cp16(uint32_t dst, const void* src) {
    asm volatile("cp.async.cg.shared.global [%0], [%1], 16;"
                 :: "r"(dst), "l"(src) : "memory");
}

// Pre-kernel: fold mask into cov (one streaming pass, high occupancy)
__global__ __launch_bounds__(256, 8)
void covmask_kernel(const float* __restrict__ cov, const int* __restrict__ mask)
{
    size_t i = ((size_t)blockIdx.x * 256 + threadIdx.x) * 4;
    float4 c = *(const float4*)(cov + i);
    int4   m = *(const int4*)(mask + i);
    float4 o;
    o.x = m.x ? c.x : -30000.0f;
    o.y = m.y ? c.y : -30000.0f;
    o.z = m.z ? c.z : -30000.0f;
    o.w = m.w ? c.w : -30000.0f;
    *(float4*)(g_covm + i) = o;
}

__global__ __launch_bounds__(NT, 1)
void attn_mma_kernel(const float* __restrict__ q,
                     const float* __restrict__ k,
                     const float* __restrict__ v,
                     const float* __restrict__ lambda_w,
                     float* __restrict__ out,      // [B,H,S,D]
                     float* __restrict__ attn)     // [B,H,S,S]
{
    extern __shared__ uint32_t sw[];
    const uint32_t sbase = (uint32_t)__cvta_generic_to_shared(sw);
    uint32_t* QW = sw + W_Q;
    uint32_t* EW = sw + W_E;
    float*    EWf = (float*)(sw + W_E);
    float*    rs = (float*)(sw + W_RS);

    const int h     = blockIdx.x;   // innermost -> heads share covm in L2
    const int mpair = blockIdx.y;   // 2 mtiles per CTA
    const int b     = blockIdx.z;
    const int bh    = b * Hq + h;
    const int tid   = threadIdx.x;
    const int wid   = tid >> 5;
    const int lane  = tid & 31;
    const int lg    = lane >> 2;    // group 0..7
    const int lt    = lane & 3;     // 0..3

    const int warp_m = wid & 3;     // row group (32 rows)
    const int warp_n = wid >> 2;    // 0..3: 16-col / 16-d slice
    const int rm = warp_m * 32;
    const int cn = warp_n * 16;
    const int dn = warp_n * 16;

    const float lam  = lambda_w[h];
    const float wcov = lam / (lam + 1.0f);
    const float sqk  = 1.0f / ((lam + 1.0f) * TEMP);

    const float* kg = k + (size_t)bh * Sq * Dq;
    const float* vg = v + (size_t)bh * Sq * Dq;

    for (int m = 0; m < 2; m++) {
        const int mtile = mpair * 2 + m;
        const float* qg    = q + ((size_t)bh * Sq + (size_t)mtile * BM) * Dq;
        const float* covg  = g_covm + ((size_t)b * Sq + (size_t)mtile * BM) * Sq;
        float*       attng = attn + ((size_t)bh * Sq + (size_t)mtile * BM) * Sq;
        float*       outg  = out  + ((size_t)bh * Sq + (size_t)mtile * BM) * Dq;

        __syncthreads();   // previous mtile fully done (QW/E/VR free)

        // ---- prefetch tile 0 (K + Vraw) ----
        {
#pragma unroll
            for (int it = 0; it < 2; it++) {
                int idx = tid + it * NT;   // 1024 16B segs each
                int t   = idx >> 4;
                int seg = idx & 15;
                cp16(sbase + (uint32_t)(W_K0  + t * KVS + seg * 4) * 4,
                     kg + (size_t)t * Dq + seg * 4);
                cp16(sbase + (uint32_t)(W_VR0 + t * KVS + seg * 4) * 4,
                     vg + (size_t)t * Dq + seg * 4);
            }
            asm volatile("cp.async.commit_group;" ::: "memory");
        }

        // ---- fill q smem (tf32) ----
#pragma unroll
        for (int it = 0; it < 4; it++) {
            int idx = tid + it * NT;        // 2048 float4
            int r  = idx >> 4;
            int c4 = (idx & 15) << 2;
            float4 f = *(const float4*)&qg[r * Dq + c4];
            uint4 o;
            o.x = f2tf32(f.x); o.y = f2tf32(f.y);
            o.z = f2tf32(f.z); o.w = f2tf32(f.w);
            *(uint4*)&QW[r * 68 + c4] = o;
        }

        float oacc[2][2][4];
#pragma unroll
        for (int mi = 0; mi < 2; mi++)
#pragma unroll
            for (int nf = 0; nf < 2; nf++)
#pragma unroll
                for (int c = 0; c < 4; c++) oacc[mi][nf][c] = 0.0f;
        float rowsum[4] = {0.0f, 0.0f, 0.0f, 0.0f};

        for (int nt = 0; nt < NTILES; nt++) {
            const int buf = nt & 1;
            const int kof = buf ? W_K1 : W_K0;
            const int vof = buf ? W_VR1 : W_VR0;
            const int t0  = nt * BN;

            // wait for current tile; barrier also proves AV(nt-1)/store(nt-1)
            // finished with smem before we overwrite anything.
            asm volatile("cp.async.wait_group 0;" ::: "memory");
            __syncthreads();

            // ---- prefetch next tile (safe: everyone past barrier) ----
            if (nt + 1 < NTILES) {
                const int kofn = buf ? W_K0 : W_K1;
                const int vofn = buf ? W_VR0 : W_VR1;
                const float* kn = kg + (size_t)(t0 + BN) * Dq;
                const float* vn = vg + (size_t)(t0 + BN) * Dq;
#pragma unroll
                for (int it = 0; it < 2; it++) {
                    int idx = tid + it * NT;
                    int t   = idx >> 4;
                    int seg = idx & 15;
                    cp16(sbase + (uint32_t)(kofn + t * KVS + seg * 4) * 4,
                         kn + (size_t)t * Dq + seg * 4);
                    cp16(sbase + (uint32_t)(vofn + t * KVS + seg * 4) * 4,
                         vn + (size_t)t * Dq + seg * 4);
                }
                asm volatile("cp.async.commit_group;" ::: "memory");
            }

            // ---- cov prefetch (hidden behind QK MMA) ----
            float2 cv[2][2][2];
#pragma unroll
            for (int mi = 0; mi < 2; mi++)
#pragma unroll
                for (int rh = 0; rh < 2; rh++) {
                    const int r = rm + mi * 16 + lg + rh * 8;
#pragma unroll
                    for (int ni = 0; ni < 2; ni++)
                        cv[mi][rh][ni] = *(const float2*)
                            (covg + (size_t)r * Sq + t0 + cn + ni * 8 + 2 * lt);
                }

            // ---- scores: warp tile 32 rows x 16 cols, tf32 mma ----
            const uint32_t* KB = sw + kof;   // natural [t][d], raw f32 as tf32
            float acc[2][2][4];
#pragma unroll
            for (int mi = 0; mi < 2; mi++)
#pragma unroll
                for (int ni = 0; ni < 2; ni++)
#pragma unroll
                    for (int c = 0; c < 4; c++) acc[mi][ni][c] = 0.0f;

#pragma unroll
            for (int ks = 0; ks < 8; ks++) {
                const int kd = ks * 8;
                uint32_t a[2][4], bb[2][2];
#pragma unroll
                for (int mi = 0; mi < 2; mi++) {
                    const uint32_t* q0 = QW + (rm + mi * 16 + lg) * 68 + kd + lt;
                    a[mi][0] = q0[0];
                    a[mi][1] = q0[8 * 68];
                    a[mi][2] = q0[4];
                    a[mi][3] = q0[8 * 68 + 4];
                }
#pragma unroll
                for (int ni = 0; ni < 2; ni++) {
                    const uint32_t* kp = KB + (cn + ni * 8 + lg) * KVS + kd + lt;
                    bb[ni][0] = kp[0];
                    bb[ni][1] = kp[4];
                }
#pragma unroll
                for (int mi = 0; mi < 2; mi++)
#pragma unroll
                    for (int ni = 0; ni < 2; ni++)
                        mma_tf32(acc[mi][ni], a[mi], bb[ni]);
            }

            // ---- epilogue: blend, exp, e (exact f32) -> EW only ----
#pragma unroll
            for (int mi = 0; mi < 2; mi++) {
#pragma unroll
                for (int rh = 0; rh < 2; rh++) {
                    const int r = rm + mi * 16 + lg + rh * 8;
                    float rsacc = 0.0f;
#pragma unroll
                    for (int ni = 0; ni < 2; ni++) {
                        const int c = cn + ni * 8 + 2 * lt;
                        float s0 = acc[mi][ni][rh * 2 + 0];
                        float s1 = acc[mi][ni][rh * 2 + 1];
                        float l0 = fmaxf(fmaf(sqk, s0, wcov * cv[mi][rh][ni].x), -60.0f);
                        float l1 = fmaxf(fmaf(sqk, s1, wcov * cv[mi][rh][ni].y), -60.0f);
                        float e0 = fexp(l0);
                        float e1 = fexp(l1);
                        rsacc += e0 + e1;
                        *(float2*)&EWf[r * ES + c] = make_float2(e0, e1);
                    }
                    rowsum[mi * 2 + rh] += rsacc;
                }
            }
            __syncthreads();

            // ---- attn store: coalesced LDS.128 -> STG.128 from EW ----
#pragma unroll
            for (int it = 0; it < 4; it++) {
                int idx = tid + it * NT;        // 2048 float4
                int r   = idx >> 4;
                int c4  = (idx & 15) << 2;
                float4 e4 = *(const float4*)&EWf[r * ES + c4];
                *(float4*)&attng[(size_t)r * Sq + t0 + c4] = e4;
            }

            // ---- AV: warp tile 32 rows x 16 d, tf32 k8, k=64 in 8 steps ----
            const float* VRf = (const float*)(sw + vof);  // natural [t][d]
#pragma unroll
            for (int ks = 0; ks < 8; ks++) {
                const int tb = ks * 8;
                uint32_t a[2][4], bb[2][2];
#pragma unroll
                for (int mi = 0; mi < 2; mi++) {
                    const float* e0 = EWf + (rm + mi * 16 + lg) * ES + tb + lt;
                    a[mi][0] = f2tf32(e0[0]);
                    a[mi][1] = f2tf32(e0[8 * ES]);
                    a[mi][2] = f2tf32(e0[4]);
                    a[mi][3] = f2tf32(e0[8 * ES + 4]);
                }
#pragma unroll
                for (int nf = 0; nf < 2; nf++) {
                    const float* vp = VRf + (tb + lt) * KVS + dn + nf * 8 + lg;
                    bb[nf][0] = f2tf32(vp[0]);
                    bb[nf][1] = f2tf32(vp[4 * KVS]);
                }
#pragma unroll
                for (int mi = 0; mi < 2; mi++)
#pragma unroll
                    for (int nf = 0; nf < 2; nf++)
                        mma_tf32(oacc[mi][nf], a[mi], bb[nf]);
            }
        }

        // ---- rowsum: reduce over lane&3, store partials ----
#pragma unroll
        for (int i = 0; i < 4; i++) {
            rowsum[i] += __shfl_xor_sync(0xffffffffu, rowsum[i], 1);
            rowsum[i] += __shfl_xor_sync(0xffffffffu, rowsum[i], 2);
        }
        __syncthreads();   // all EW/VR reads done before rs region reuse
        if (lt == 0) {
#pragma unroll
            for (int mi = 0; mi < 2; mi++)
#pragma unroll
                for (int rh = 0; rh < 2; rh++)
                    rs[warp_n * 128 + rm + mi * 16 + lg + rh * 8] = rowsum[mi * 2 + rh];
        }
        __syncthreads();

        // ---- write normalized output ----
#pragma unroll
        for (int mi = 0; mi < 2; mi++) {
#pragma unroll
            for (int rh = 0; rh < 2; rh++) {
                const int r = rm + mi * 16 + lg + rh * 8;
                const float iv = 1.0f /
                    (rs[r] + rs[128 + r] + rs[256 + r] + rs[384 + r]);
#pragma unroll
                for (int nf = 0; nf < 2; nf++) {
                    const int d = dn + nf * 8 + 2 * lt;
                    float2 o;
                    o.x = oacc[mi][nf][rh * 2 + 0] * iv;
                    o.y = oacc[mi][nf][rh * 2 + 1] * iv;
                    *(float2*)(outg + (size_t)r * Dq + d) = o;
                }
            }
        }

        // ---- fused normalize tail: scale this mtile's attn slice ----
        {
            const int rlane = tid >> 7;          // 0..3
            const int ci    = tid & 127;         // float4 col
#pragma unroll 2
            for (int rb = 0; rb < 32; rb++) {
                const int r = rb * 4 + rlane;
                const float iv = 1.0f /
                    (rs[r] + rs[128 + r] + rs[256 + r] + rs[384 + r]);
                float4* arow = (float4*)(attng + (size_t)r * Sq);
                float4 x0 = arow[ci];
                float4 x1 = arow[ci + 128];
                float4 x2 = arow[ci + 256];
                float4 x3 = arow[ci + 384];
                x0.x *= iv; x0.y *= iv; x0.z *= iv; x0.w *= iv;
                x1.x *= iv; x1.y *= iv; x1.z *= iv; x1.w *= iv;
                x2.x *= iv; x2.y *= iv; x2.z *= iv; x2.w *= iv;
                x3.x *= iv; x3.y *= iv; x3.z *= iv; x3.w *= iv;
                arow[ci]       = x0;
                arow[ci + 128] = x1;
                arow[ci + 256] = x2;
                arow[ci + 384] = x3;
            }
        }
    }
}

extern "C" void kernel_launch(void* const* d_in, const int* in_sizes, int n_in,
                              void* d_out, int out_size)
{
    const float* q    = (const float*)d_in[0];
    const float* k    = (const float*)d_in[1];
    const float* v    = (const float*)d_in[2];
    const float* cov  = (const float*)d_in[3];
    const float* lam  = (const float*)d_in[4];
    const int*   mask = (const int*)d_in[5];

    float* out  = (float*)d_out;                          // [B,H,S,D]
    float* attn = out + (size_t)Bq * Hq * Sq * Dq;        // [B,H,S,S]

    // pass 0: fold mask into cov (streaming, ~14 us)
    const size_t n4 = (size_t)Bq * Sq * Sq / 4;
    covmask_kernel<<<(unsigned)(n4 / 256), 256>>>(cov, mask);

    cudaFuncSetAttribute(attn_mma_kernel,
                         cudaFuncAttributeMaxDynamicSharedMemorySize, SMEM_BYTES);
    dim3 grid(Hq, Sq / BM / 2, Bq);  // (8, 8, 2) = 128 CTAs, single wave
    attn_mma_kernel<<<grid, NT, SMEM_BYTES>>>(q, k, v, lam, out, attn);
}

// round 14
// speedup vs baseline: 1.0755x; 1.0144x over previous
#include <cuda_runtime.h>
#include <cstdint>

#define Bq 2
#define Hq 8
#define Sq 2048
#define Dq 64
#define TEMP 8.0f

#define BM 128
#define BN 64
#define NT 512
#define NTILES (Sq / BN)   // 32

// smem word offsets
#define W_Q   0                      // q tf32 [128][68] (staging only)
#define W_K0  8704                   // k raw f32 [64][68] natural [t][d], buf 0
#define W_K1  13056                  // buf 1
#define W_VR0 17408                  // v raw f32 [64][68] natural [t][d], buf 0
#define W_VR1 21760                  // buf 1
#define W_E   26112                  // e tf32-rounded [128][76] ([row][t])
#define W_RS  35840                  // rowsum [4][128] floats
#define W_QF  36352                  // packed Q fragments, 8192 words
#define SMEM_WORDS 44544
#define SMEM_BYTES (SMEM_WORDS * 4)  // 178176 B

#define KVS 68     // K / Vraw row stride (words)
#define ES  76     // E row stride (words)

// masked-cov scratch: covm = mask ? cov : -3e4   (33.5 MB)
__device__ float g_covm[(size_t)Bq * Sq * Sq];

static __device__ __forceinline__ uint32_t f2tf32(float f) {
    uint32_t r;
    asm("cvt.rna.tf32.f32 %0, %1;" : "=r"(r) : "f"(f));
    return r;
}
// exp(x) on fma/alu pipes only (no MUFU). Caller clamps x >= -60.
static __device__ __forceinline__ float fexp(float x) {
    const float L2E = 1.4426950408889634f;
    float t = fmaf(x, L2E, 12582912.0f);          // 1.5*2^23: rounds to int
    int   in = __float_as_int(t);
    float n  = t - 12582912.0f;
    float z  = fmaf(x, L2E, -n);                  // frac in [-0.5, 0.5]
    float w  = z * 0.6931471805599453f;
    float p  = fmaf(w, 4.1666667e-2f, 0.16666667f);   // degree-4
    p = fmaf(p, w, 0.5f);
    p = fmaf(p, w, 1.0f);
    p = fmaf(p, w, 1.0f);
    return __int_as_float(__float_as_int(p) + (in << 23));
}
static __device__ __forceinline__ void mma_tf32(float* d, const uint32_t* a,
                                                const uint32_t* b) {
    asm volatile(
        "mma.sync.aligned.m16n8k8.row.col.f32.tf32.tf32.f32 "
        "{%0,%1,%2,%3}, {%4,%5,%6,%7}, {%8,%9}, {%0,%1,%2,%3};"
        : "+f"(d[0]), "+f"(d[1]), "+f"(d[2]), "+f"(d[3])
        : "r"(a[0]), "r"(a[1]), "r"(a[2]), "r"(a[3]), "r"(b[0]), "r"(b[1]));
}
static __device__ __forceinline__ void cp16(uint32_t dst, const void* src) {
    asm volatile("cp.async.cg.shared.global [%0], [%1], 16;"
                 :: "r"(dst), "l"(src) : "memory");
}

// Pre-kernel: fold mask into cov (one streaming pass, high occupancy)
__global__ __launch_bounds__(256, 8)
void covmask_kernel(const float* __restrict__ cov, const int* __restrict__ mask)
{
    size_t i = ((size_t)blockIdx.x * 256 + threadIdx.x) * 4;
    float4 c = *(const float4*)(cov + i);
    int4   m = *(const int4*)(mask + i);
    float4 o;
    o.x = m.x ? c.x : -30000.0f;
    o.y = m.y ? c.y : -30000.0f;
    o.z = m.z ? c.z : -30000.0f;
    o.w = m.w ? c.w : -30000.0f;
    *(float4*)(g_covm + i) = o;
}

__global__ __launch_bounds__(NT, 1)
void attn_mma_kernel(const float* __restrict__ q,
                     const float* __restrict__ k,
                     const float* __restrict__ v,
                     const float* __restrict__ lambda_w,
                     float* __restrict__ out,      // [B,H,S,D]
                     float* __restrict__ attn)     // [B,H,S,S]
{
    extern __shared__ uint32_t sw[];
    const uint32_t sbase = (uint32_t)__cvta_generic_to_shared(sw);
    uint32_t* QW  = sw + W_Q;
    uint32_t* QF  = sw + W_QF;
    uint32_t* EW  = sw + W_E;
    float*    EWf = (float*)(sw + W_E);
    float*    rs  = (float*)(sw + W_RS);

    const int h     = blockIdx.x;   // innermost -> heads share covm in L2
    const int mpair = blockIdx.y;   // 2 mtiles per CTA
    const int b     = blockIdx.z;
    const int bh    = b * Hq + h;
    const int tid   = threadIdx.x;
    const int wid   = tid >> 5;
    const int lane  = tid & 31;
    const int lg    = lane >> 2;    // group 0..7
    const int lt    = lane & 3;     // 0..3

    const int warp_m = wid & 3;     // row group (32 rows)
    const int warp_n = wid >> 2;    // 0..3: 16-col / 16-d slice
    const int rm = warp_m * 32;
    const int cn = warp_n * 16;
    const int dn = warp_n * 16;

    const float lam  = lambda_w[h];
    const float wcov = lam / (lam + 1.0f);
    const float sqk  = 1.0f / ((lam + 1.0f) * TEMP);

    const float* kg = k + (size_t)bh * Sq * Dq;
    const float* vg = v + (size_t)bh * Sq * Dq;

    for (int m = 0; m < 2; m++) {
        const int mtile = mpair * 2 + m;
        const float* qg    = q + ((size_t)bh * Sq + (size_t)mtile * BM) * Dq;
        const float* covg  = g_covm + ((size_t)b * Sq + (size_t)mtile * BM) * Sq;
        float*       attng = attn + ((size_t)bh * Sq + (size_t)mtile * BM) * Sq;
        float*       outg  = out  + ((size_t)bh * Sq + (size_t)mtile * BM) * Dq;

        __syncthreads();   // previous mtile fully done (all smem free)

        // ---- prefetch tile 0 (K + Vraw) ----
        {
#pragma unroll
            for (int it = 0; it < 2; it++) {
                int idx = tid + it * NT;   // 1024 16B segs each
                int t   = idx >> 4;
                int seg = idx & 15;
                cp16(sbase + (uint32_t)(W_K0  + t * KVS + seg * 4) * 4,
                     kg + (size_t)t * Dq + seg * 4);
                cp16(sbase + (uint32_t)(W_VR0 + t * KVS + seg * 4) * 4,
                     vg + (size_t)t * Dq + seg * 4);
            }
            asm volatile("cp.async.commit_group;" ::: "memory");
        }

        // ---- fill q staging smem (tf32) ----
#pragma unroll
        for (int it = 0; it < 4; it++) {
            int idx = tid + it * NT;        // 2048 float4
            int r  = idx >> 4;
            int c4 = (idx & 15) << 2;
            float4 f = *(const float4*)&qg[r * Dq + c4];
            uint4 o;
            o.x = f2tf32(f.x); o.y = f2tf32(f.y);
            o.z = f2tf32(f.z); o.w = f2tf32(f.w);
            *(uint4*)&QW[r * 68 + c4] = o;
        }
        __syncthreads();

        // ---- pack Q fragments: QF[ks][warp_m][mi][lane][0..3] ----
        // warp (warp_m, warp_n) packs ks in {2*warp_n, 2*warp_n+1}
#pragma unroll
        for (int kk = 0; kk < 2; kk++) {
            const int ks = warp_n * 2 + kk;
            const int d0 = ks * 8 + lt;
#pragma unroll
            for (int mi = 0; mi < 2; mi++) {
                const int r0 = rm + mi * 16 + lg;
                uint4 fr;
                fr.x = QW[r0 * 68 + d0];
                fr.y = QW[(r0 + 8) * 68 + d0];
                fr.z = QW[r0 * 68 + d0 + 4];
                fr.w = QW[(r0 + 8) * 68 + d0 + 4];
                *(uint4*)&QF[((((ks * 4 + warp_m) * 2 + mi) * 32) + lane) * 4] = fr;
            }
        }

        float oacc[2][2][4];
#pragma unroll
        for (int mi = 0; mi < 2; mi++)
#pragma unroll
            for (int nf = 0; nf < 2; nf++)
#pragma unroll
                for (int c = 0; c < 4; c++) oacc[mi][nf][c] = 0.0f;
        float rowsum[4] = {0.0f, 0.0f, 0.0f, 0.0f};

        for (int nt = 0; nt < NTILES; nt++) {
            const int buf = nt & 1;
            const int kof = buf ? W_K1 : W_K0;
            const int vof = buf ? W_VR1 : W_VR0;
            const int t0  = nt * BN;

            // wait for current tile; barrier also proves AV(nt-1)/store(nt-1)
            // finished with smem (and QF pack visible on nt==0).
            asm volatile("cp.async.wait_group 0;" ::: "memory");
            __syncthreads();

            // ---- prefetch next tile (safe: everyone past barrier) ----
            if (nt + 1 < NTILES) {
                const int kofn = buf ? W_K0 : W_K1;
                const int vofn = buf ? W_VR0 : W_VR1;
                const float* kn = kg + (size_t)(t0 + BN) * Dq;
                const float* vn = vg + (size_t)(t0 + BN) * Dq;
#pragma unroll
                for (int it = 0; it < 2; it++) {
                    int idx = tid + it * NT;
                    int t   = idx >> 4;
                    int seg = idx & 15;
                    cp16(sbase + (uint32_t)(kofn + t * KVS + seg * 4) * 4,
                         kn + (size_t)t * Dq + seg * 4);
                    cp16(sbase + (uint32_t)(vofn + t * KVS + seg * 4) * 4,
                         vn + (size_t)t * Dq + seg * 4);
                }
                asm volatile("cp.async.commit_group;" ::: "memory");
            }

            // ---- cov prefetch (hidden behind QK MMA) ----
            float2 cv[2][2][2];
#pragma unroll
            for (int mi = 0; mi < 2; mi++)
#pragma unroll
                for (int rh = 0; rh < 2; rh++) {
                    const int r = rm + mi * 16 + lg + rh * 8;
#pragma unroll
                    for (int ni = 0; ni < 2; ni++)
                        cv[mi][rh][ni] = *(const float2*)
                            (covg + (size_t)r * Sq + t0 + cn + ni * 8 + 2 * lt);
                }

            // ---- scores: warp tile 32 rows x 16 cols, tf32 mma ----
            const uint32_t* KB = sw + kof;   // natural [t][d], raw f32 as tf32
            float acc[2][2][4];
#pragma unroll
            for (int mi = 0; mi < 2; mi++)
#pragma unroll
                for (int ni = 0; ni < 2; ni++)
#pragma unroll
                    for (int c = 0; c < 4; c++) acc[mi][ni][c] = 0.0f;

#pragma unroll
            for (int ks = 0; ks < 8; ks++) {
                const int kd = ks * 8;
                uint32_t a[2][4], bb[2][2];
#pragma unroll
                for (int mi = 0; mi < 2; mi++) {
                    uint4 fr = *(const uint4*)
                        &QF[((((ks * 4 + warp_m) * 2 + mi) * 32) + lane) * 4];
                    a[mi][0] = fr.x; a[mi][1] = fr.y;
                    a[mi][2] = fr.z; a[mi][3] = fr.w;
                }
#pragma unroll
                for (int ni = 0; ni < 2; ni++) {
                    const uint32_t* kp = KB + (cn + ni * 8 + lg) * KVS + kd + lt;
                    bb[ni][0] = kp[0];
                    bb[ni][1] = kp[4];
                }
#pragma unroll
                for (int mi = 0; mi < 2; mi++)
#pragma unroll
                    for (int ni = 0; ni < 2; ni++)
                        mma_tf32(acc[mi][ni], a[mi], bb[ni]);
            }

            // ---- epilogue: blend, exp, e (tf32-rounded) -> EW ----
#pragma unroll
            for (int mi = 0; mi < 2; mi++) {
#pragma unroll
                for (int rh = 0; rh < 2; rh++) {
                    const int r = rm + mi * 16 + lg + rh * 8;
                    float rsacc = 0.0f;
#pragma unroll
                    for (int ni = 0; ni < 2; ni++) {
                        const int c = cn + ni * 8 + 2 * lt;
                        float s0 = acc[mi][ni][rh * 2 + 0];
                        float s1 = acc[mi][ni][rh * 2 + 1];
                        float l0 = fmaxf(fmaf(sqk, s0, wcov * cv[mi][rh][ni].x), -60.0f);
                        float l1 = fmaxf(fmaf(sqk, s1, wcov * cv[mi][rh][ni].y), -60.0f);
                        uint32_t u0 = f2tf32(fexp(l0));
                        uint32_t u1 = f2tf32(fexp(l1));
                        rsacc += __uint_as_float(u0) + __uint_as_float(u1);
                        *(uint2*)&EW[r * ES + c] = make_uint2(u0, u1);
                    }
                    rowsum[mi * 2 + rh] += rsacc;
                }
            }
            __syncthreads();

            // ---- attn store: coalesced LDS.128 -> STG.128 from EW ----
#pragma unroll
            for (int it = 0; it < 4; it++) {
                int idx = tid + it * NT;        // 2048 float4
                int r   = idx >> 4;
                int c4  = (idx & 15) << 2;
                float4 e4 = *(const float4*)&EWf[r * ES + c4];
                *(float4*)&attng[(size_t)r * Sq + t0 + c4] = e4;
            }

            // ---- AV: warp tile 32 rows x 16 d, tf32 k8, k=64 in 8 steps ----
            const float* VRf = (const float*)(sw + vof);  // natural [t][d]
#pragma unroll
            for (int ks = 0; ks < 8; ks++) {
                const int tb = ks * 8;
                uint32_t a[2][4], bb[2][2];
#pragma unroll
                for (int mi = 0; mi < 2; mi++) {
                    const uint32_t* e0 = EW + (rm + mi * 16 + lg) * ES + tb + lt;
                    a[mi][0] = e0[0];
                    a[mi][1] = e0[8 * ES];
                    a[mi][2] = e0[4];
                    a[mi][3] = e0[8 * ES + 4];
                }
#pragma unroll
                for (int nf = 0; nf < 2; nf++) {
                    const float* vp = VRf + (tb + lt) * KVS + dn + nf * 8 + lg;
                    bb[nf][0] = f2tf32(vp[0]);
                    bb[nf][1] = f2tf32(vp[4 * KVS]);
                }
#pragma unroll
                for (int mi = 0; mi < 2; mi++)
#pragma unroll
                    for (int nf = 0; nf < 2; nf++)
                        mma_tf32(oacc[mi][nf], a[mi], bb[nf]);
            }
        }

        // ---- rowsum: reduce over lane&3, store partials ----
#pragma unroll
        for (int i = 0; i < 4; i++) {
            rowsum[i] += __shfl_xor_sync(0xffffffffu, rowsum[i], 1);
            rowsum[i] += __shfl_xor_sync(0xffffffffu, rowsum[i], 2);
        }
        __syncthreads();   // all EW/VR reads done before rs region reuse
        if (lt == 0) {
#pragma unroll
            for (int mi = 0; mi < 2; mi++)
#pragma unroll
                for (int rh = 0; rh < 2; rh++)
                    rs[warp_n * 128 + rm + mi * 16 + lg + rh * 8] = rowsum[mi * 2 + rh];
        }
        __syncthreads();

        // ---- write normalized output ----
#pragma unroll
        for (int mi = 0; mi < 2; mi++) {
#pragma unroll
            for (int rh = 0; rh < 2; rh++) {
                const int r = rm + mi * 16 + lg + rh * 8;
                const float iv = 1.0f /
                    (rs[r] + rs[128 + r] + rs[256 + r] + rs[384 + r]);
#pragma unroll
                for (int nf = 0; nf < 2; nf++) {
                    const int d = dn + nf * 8 + 2 * lt;
                    float2 o;
                    o.x = oacc[mi][nf][rh * 2 + 0] * iv;
                    o.y = oacc[mi][nf][rh * 2 + 1] * iv;
                    *(float2*)(outg + (size_t)r * Dq + d) = o;
                }
            }
        }

        // ---- fused normalize tail: scale this mtile's attn slice ----
        {
            const int rlane = tid >> 7;          // 0..3
            const int ci    = tid & 127;         // float4 col
#pragma unroll 2
            for (int rb = 0; rb < 32; rb++) {
                const int r = rb * 4 + rlane;
                const float iv = 1.0f /
                    (rs[r] + rs[128 + r] + rs[256 + r] + rs[384 + r]);
                float4* arow = (float4*)(attng + (size_t)r * Sq);
                float4 x0 = arow[ci];
                float4 x1 = arow[ci + 128];
                float4 x2 = arow[ci + 256];
                float4 x3 = arow[ci + 384];
                x0.x *= iv; x0.y *= iv; x0.z *= iv; x0.w *= iv;
                x1.x *= iv; x1.y *= iv; x1.z *= iv; x1.w *= iv;
                x2.x *= iv; x2.y *= iv; x2.z *= iv; x2.w *= iv;
                x3.x *= iv; x3.y *= iv; x3.z *= iv; x3.w *= iv;
                arow[ci]       = x0;
                arow[ci + 128] = x1;
                arow[ci + 256] = x2;
                arow[ci + 384] = x3;
            }
        }
    }
}

extern "C" void kernel_launch(void* const* d_in, const int* in_sizes, int n_in,
                              void* d_out, int out_size)
{
    const float* q    = (const float*)d_in[0];
    const float* k    = (const float*)d_in[1];
    const float* v    = (const float*)d_in[2];
    const float* cov  = (const float*)d_in[3];
    const float* lam  = (const float*)d_in[4];
    const int*   mask = (const int*)d_in[5];

    float* out  = (float*)d_out;                          // [B,H,S,D]
    float* attn = out + (size_t)Bq * Hq * Sq * Dq;        // [B,H,S,S]

    // pass 0: fold mask into cov (streaming, ~14 us)
    const size_t n4 = (size_t)Bq * Sq * Sq / 4;
    covmask_kernel<<<(unsigned)(n4 / 256), 256>>>(cov, mask);

    cudaFuncSetAttribute(attn_mma_kernel,
                         cudaFuncAttributeMaxDynamicSharedMemorySize, SMEM_BYTES);
    dim3 grid(Hq, Sq / BM / 2, Bq);  // (8, 8, 2) = 128 CTAs, single wave
    attn_mma_kernel<<<grid, NT, SMEM_BYTES>>>(q, k, v, lam, out, attn);
}

// round 15
// speedup vs baseline: 1.1322x; 1.0528x over previous
#include <cuda_runtime.h>
#include <cstdint>

#define Bq 2
#define Hq 8
#define Sq 2048
#define Dq 64
#define TEMP 8.0f

#define BM 128
#define BN 64
#define NT 512
#define NTILES (Sq / BN)   // 32

// smem word offsets
#define W_Q   0                      // q tf32 [128][68]
#define W_K0  8704                   // k raw f32 [64][68] natural [t][d], buf 0
#define W_K1  13056                  // buf 1
#define W_VR0 17408                  // v raw f32 [64][68] natural [t][d], buf 0
#define W_VR1 21760                  // buf 1
#define W_E   26112                  // e tf32-rounded [128][76] ([row][t])
#define W_RS  35840                  // rowsum [4][128] floats
#define W_CV0 36352                  // cov tile f32 [128][72], buf 0
#define W_CV1 45568                  // buf 1
#define SMEM_WORDS 54784
#define SMEM_BYTES (SMEM_WORDS * 4)  // 219136 B -> 1 CTA/SM

#define KVS 68     // K / Vraw row stride (words)
#define ES  76     // E row stride (words)
#define CVS 72     // cov tile row stride (words): LDS.64 conflict-free

// masked-cov scratch: covm = mask ? cov : -3e4   (33.5 MB)
__device__ float g_covm[(size_t)Bq * Sq * Sq];

static __device__ __forceinline__ uint32_t f2tf32(float f) {
    uint32_t r;
    asm("cvt.rna.tf32.f32 %0, %1;" : "=r"(r) : "f"(f));
    return r;
}
// exp(x) on fma/alu pipes only (no MUFU). Caller clamps x >= -60.
static __device__ __forceinline__ float fexp(float x) {
    const float L2E = 1.4426950408889634f;
    float t = fmaf(x, L2E, 12582912.0f);          // 1.5*2^23: rounds to int
    int   in = __float_as_int(t);
    float n  = t - 12582912.0f;
    float z  = fmaf(x, L2E, -n);                  // frac in [-0.5, 0.5]
    float w  = z * 0.6931471805599453f;
    float p  = fmaf(w, 4.1666667e-2f, 0.16666667f);   // degree-4
    p = fmaf(p, w, 0.5f);
    p = fmaf(p, w, 1.0f);
    p = fmaf(p, w, 1.0f);
    return __int_as_float(__float_as_int(p) + (in << 23));
}
static __device__ __forceinline__ void mma_tf32(float* d, const uint32_t* a,
                                                const uint32_t* b) {
    asm volatile(
        "mma.sync.aligned.m16n8k8.row.col.f32.tf32.tf32.f32 "
        "{%0,%1,%2,%3}, {%4,%5,%6,%7}, {%8,%9}, {%0,%1,%2,%3};"
        : "+f"(d[0]), "+f"(d[1]), "+f"(d[2]), "+f"(d[3])
        : "r"(a[0]), "r"(a[1]), "r"(a[2]), "r"(a[3]), "r"(b[0]), "r"(b[1]));
}
static __device__ __forceinline__ void cp16(uint32_t dst, const void* src) {
    asm volatile("cp.async.cg.shared.global [%0], [%1], 16;"
                 :: "r"(dst), "l"(src) : "memory");
}

// Pre-kernel: fold mask into cov (one streaming pass, high occupancy)
__global__ __launch_bounds__(256, 8)
void covmask_kernel(const float* __restrict__ cov, const int* __restrict__ mask)
{
    size_t i = ((size_t)blockIdx.x * 256 + threadIdx.x) * 4;
    float4 c = *(const float4*)(cov + i);
    int4   m = *(const int4*)(mask + i);
    float4 o;
    o.x = m.x ? c.x : -30000.0f;
    o.y = m.y ? c.y : -30000.0f;
    o.z = m.z ? c.z : -30000.0f;
    o.w = m.w ? c.w : -30000.0f;
    *(float4*)(g_covm + i) = o;
}

__global__ __launch_bounds__(NT, 1)
void attn_mma_kernel(const float* __restrict__ q,
                     const float* __restrict__ k,
                     const float* __restrict__ v,
                     const float* __restrict__ lambda_w,
                     float* __restrict__ out,      // [B,H,S,D]
                     float* __restrict__ attn)     // [B,H,S,S]
{
    extern __shared__ uint32_t sw[];
    const uint32_t sbase = (uint32_t)__cvta_generic_to_shared(sw);
    uint32_t* QW  = sw + W_Q;
    uint32_t* EW  = sw + W_E;
    float*    EWf = (float*)(sw + W_E);
    float*    rs  = (float*)(sw + W_RS);

    const int h     = blockIdx.x;   // innermost -> heads share covm in L2
    const int mpair = blockIdx.y;   // 2 mtiles per CTA
    const int b     = blockIdx.z;
    const int bh    = b * Hq + h;
    const int tid   = threadIdx.x;
    const int wid   = tid >> 5;
    const int lane  = tid & 31;
    const int lg    = lane >> 2;    // group 0..7
    const int lt    = lane & 3;     // 0..3

    const int warp_m = wid & 3;     // row group (32 rows)
    const int warp_n = wid >> 2;    // 0..3: 16-col / 16-d slice
    const int rm = warp_m * 32;
    const int cn = warp_n * 16;
    const int dn = warp_n * 16;

    const float lam  = lambda_w[h];
    const float wcov = lam / (lam + 1.0f);
    const float sqk  = 1.0f / ((lam + 1.0f) * TEMP);

    const float* kg = k + (size_t)bh * Sq * Dq;
    const float* vg = v + (size_t)bh * Sq * Dq;

    for (int m = 0; m < 2; m++) {
        const int mtile = mpair * 2 + m;
        const float* qg    = q + ((size_t)bh * Sq + (size_t)mtile * BM) * Dq;
        const float* covg  = g_covm + ((size_t)b * Sq + (size_t)mtile * BM) * Sq;
        float*       attng = attn + ((size_t)bh * Sq + (size_t)mtile * BM) * Sq;
        float*       outg  = out  + ((size_t)bh * Sq + (size_t)mtile * BM) * Dq;

        __syncthreads();   // previous mtile fully done (all smem free)

        // ---- prefetch tile 0 (K + Vraw + cov) ----
        {
#pragma unroll
            for (int it = 0; it < 2; it++) {
                int idx = tid + it * NT;   // 1024 16B segs each
                int t   = idx >> 4;
                int seg = idx & 15;
                cp16(sbase + (uint32_t)(W_K0  + t * KVS + seg * 4) * 4,
                     kg + (size_t)t * Dq + seg * 4);
                cp16(sbase + (uint32_t)(W_VR0 + t * KVS + seg * 4) * 4,
                     vg + (size_t)t * Dq + seg * 4);
            }
#pragma unroll
            for (int it = 0; it < 4; it++) {
                int idx = tid + it * NT;   // 2048 segs: 128 rows x 16 segs
                int r   = idx >> 4;
                int seg = idx & 15;
                cp16(sbase + (uint32_t)(W_CV0 + r * CVS + seg * 4) * 4,
                     covg + (size_t)r * Sq + seg * 4);
            }
            asm volatile("cp.async.commit_group;" ::: "memory");
        }

        // ---- fill q smem (tf32) ----
#pragma unroll
        for (int it = 0; it < 4; it++) {
            int idx = tid + it * NT;        // 2048 float4
            int r  = idx >> 4;
            int c4 = (idx & 15) << 2;
            float4 f = *(const float4*)&qg[r * Dq + c4];
            uint4 o;
            o.x = f2tf32(f.x); o.y = f2tf32(f.y);
            o.z = f2tf32(f.z); o.w = f2tf32(f.w);
            *(uint4*)&QW[r * 68 + c4] = o;
        }

        float oacc[2][2][4];
#pragma unroll
        for (int mi = 0; mi < 2; mi++)
#pragma unroll
            for (int nf = 0; nf < 2; nf++)
#pragma unroll
                for (int c = 0; c < 4; c++) oacc[mi][nf][c] = 0.0f;
        float rowsum[4] = {0.0f, 0.0f, 0.0f, 0.0f};

        for (int nt = 0; nt < NTILES; nt++) {
            const int buf = nt & 1;
            const int kof  = buf ? W_K1  : W_K0;
            const int vof  = buf ? W_VR1 : W_VR0;
            const int cvof = buf ? W_CV1 : W_CV0;
            const int t0  = nt * BN;

            // wait for current tile; barrier also proves phase(nt-1) readers
            // are done with the buffers we're about to overwrite.
            asm volatile("cp.async.wait_group 0;" ::: "memory");
            __syncthreads();

            // ---- prefetch next tile (K + V + cov) ----
            if (nt + 1 < NTILES) {
                const int kofn  = buf ? W_K0  : W_K1;
                const int vofn  = buf ? W_VR0 : W_VR1;
                const int cvofn = buf ? W_CV0 : W_CV1;
                const float* kn = kg + (size_t)(t0 + BN) * Dq;
                const float* vn = vg + (size_t)(t0 + BN) * Dq;
                const float* cvn = covg + t0 + BN;
#pragma unroll
                for (int it = 0; it < 2; it++) {
                    int idx = tid + it * NT;
                    int t   = idx >> 4;
                    int seg = idx & 15;
                    cp16(sbase + (uint32_t)(kofn + t * KVS + seg * 4) * 4,
                         kn + (size_t)t * Dq + seg * 4);
                    cp16(sbase + (uint32_t)(vofn + t * KVS + seg * 4) * 4,
                         vn + (size_t)t * Dq + seg * 4);
                }
#pragma unroll
                for (int it = 0; it < 4; it++) {
                    int idx = tid + it * NT;
                    int r   = idx >> 4;
                    int seg = idx & 15;
                    cp16(sbase + (uint32_t)(cvofn + r * CVS + seg * 4) * 4,
                         cvn + (size_t)r * Sq + seg * 4);
                }
                asm volatile("cp.async.commit_group;" ::: "memory");
            }

            // ---- scores: warp tile 32 rows x 16 cols, tf32 mma ----
            const uint32_t* KB = sw + kof;   // natural [t][d], raw f32 as tf32
            float acc[2][2][4];
#pragma unroll
            for (int mi = 0; mi < 2; mi++)
#pragma unroll
                for (int ni = 0; ni < 2; ni++)
#pragma unroll
                    for (int c = 0; c < 4; c++) acc[mi][ni][c] = 0.0f;

#pragma unroll
            for (int ks = 0; ks < 8; ks++) {
                const int kd = ks * 8;
                uint32_t a[2][4], bb[2][2];
#pragma unroll
                for (int mi = 0; mi < 2; mi++) {
                    const uint32_t* q0 = QW + (rm + mi * 16 + lg) * 68 + kd + lt;
                    a[mi][0] = q0[0];
                    a[mi][1] = q0[8 * 68];
                    a[mi][2] = q0[4];
                    a[mi][3] = q0[8 * 68 + 4];
                }
#pragma unroll
                for (int ni = 0; ni < 2; ni++) {
                    const uint32_t* kp = KB + (cn + ni * 8 + lg) * KVS + kd + lt;
                    bb[ni][0] = kp[0];
                    bb[ni][1] = kp[4];
                }
#pragma unroll
                for (int mi = 0; mi < 2; mi++)
#pragma unroll
                    for (int ni = 0; ni < 2; ni++)
                        mma_tf32(acc[mi][ni], a[mi], bb[ni]);
            }

            // ---- epilogue: blend (cov from smem), exp, e -> EW ----
            const float* CVf = (const float*)(sw + cvof);
#pragma unroll
            for (int mi = 0; mi < 2; mi++) {
#pragma unroll
                for (int rh = 0; rh < 2; rh++) {
                    const int r = rm + mi * 16 + lg + rh * 8;
                    float rsacc = 0.0f;
#pragma unroll
                    for (int ni = 0; ni < 2; ni++) {
                        const int c = cn + ni * 8 + 2 * lt;
                        float2 cvv = *(const float2*)&CVf[r * CVS + c];
                        float s0 = acc[mi][ni][rh * 2 + 0];
                        float s1 = acc[mi][ni][rh * 2 + 1];
                        float l0 = fmaxf(fmaf(sqk, s0, wcov * cvv.x), -60.0f);
                        float l1 = fmaxf(fmaf(sqk, s1, wcov * cvv.y), -60.0f);
                        uint32_t u0 = f2tf32(fexp(l0));
                        uint32_t u1 = f2tf32(fexp(l1));
                        rsacc += __uint_as_float(u0) + __uint_as_float(u1);
                        *(uint2*)&EW[r * ES + c] = make_uint2(u0, u1);
                    }
                    rowsum[mi * 2 + rh] += rsacc;
                }
            }
            __syncthreads();

            // ---- attn store: coalesced LDS.128 -> STG.128 from EW ----
#pragma unroll
            for (int it = 0; it < 4; it++) {
                int idx = tid + it * NT;        // 2048 float4
                int r   = idx >> 4;
                int c4  = (idx & 15) << 2;
                float4 e4 = *(const float4*)&EWf[r * ES + c4];
                *(float4*)&attng[(size_t)r * Sq + t0 + c4] = e4;
            }

            // ---- AV: warp tile 32 rows x 16 d, tf32 k8, k=64 in 8 steps ----
            const float* VRf = (const float*)(sw + vof);  // natural [t][d]
#pragma unroll
            for (int ks = 0; ks < 8; ks++) {
                const int tb = ks * 8;
                uint32_t a[2][4], bb[2][2];
#pragma unroll
                for (int mi = 0; mi < 2; mi++) {
                    const uint32_t* e0 = EW + (rm + mi * 16 + lg) * ES + tb + lt;
                    a[mi][0] = e0[0];
                    a[mi][1] = e0[8 * ES];
                    a[mi][2] = e0[4];
                    a[mi][3] = e0[8 * ES + 4];
                }
#pragma unroll
                for (int nf = 0; nf < 2; nf++) {
                    const float* vp = VRf + (tb + lt) * KVS + dn + nf * 8 + lg;
                    bb[nf][0] = f2tf32(vp[0]);
                    bb[nf][1] = f2tf32(vp[4 * KVS]);
                }
#pragma unroll
                for (int mi = 0; mi < 2; mi++)
#pragma unroll
                    for (int nf = 0; nf < 2; nf++)
                        mma_tf32(oacc[mi][nf], a[mi], bb[nf]);
            }
        }

        // ---- rowsum: reduce over lane&3, store partials ----
#pragma unroll
        for (int i = 0; i < 4; i++) {
            rowsum[i] += __shfl_xor_sync(0xffffffffu, rowsum[i], 1);
            rowsum[i] += __shfl_xor_sync(0xffffffffu, rowsum[i], 2);
        }
        __syncthreads();   // all EW/VR reads done before rs region reuse
        if (lt == 0) {
#pragma unroll
            for (int mi = 0; mi < 2; mi++)
#pragma unroll
                for (int rh = 0; rh < 2; rh++)
                    rs[warp_n * 128 + rm + mi * 16 + lg + rh * 8] = rowsum[mi * 2 + rh];
        }
        __syncthreads();

        // ---- write normalized output ----
#pragma unroll
        for (int mi = 0; mi < 2; mi++) {
#pragma unroll
            for (int rh = 0; rh < 2; rh++) {
                const int r = rm + mi * 16 + lg + rh * 8;
                const float iv = 1.0f /
                    (rs[r] + rs[128 + r] + rs[256 + r] + rs[384 + r]);
#pragma unroll
                for (int nf = 0; nf < 2; nf++) {
                    const int d = dn + nf * 8 + 2 * lt;
                    float2 o;
                    o.x = oacc[mi][nf][rh * 2 + 0] * iv;
                    o.y = oacc[mi][nf][rh * 2 + 1] * iv;
                    *(float2*)(outg + (size_t)r * Dq + d) = o;
                }
            }
        }

        // ---- fused normalize tail: scale this mtile's attn slice ----
        {
            const int rlane = tid >> 7;          // 0..3
            const int ci    = tid & 127;         // float4 col
#pragma unroll 2
            for (int rb = 0; rb < 32; rb++) {
                const int r = rb * 4 + rlane;
                const float iv = 1.0f /
                    (rs[r] + rs[128 + r] + rs[256 + r] + rs[384 + r]);
                float4* arow = (float4*)(attng + (size_t)r * Sq);
                float4 x0 = arow[ci];
                float4 x1 = arow[ci + 128];
                float4 x2 = arow[ci + 256];
                float4 x3 = arow[ci + 384];
                x0.x *= iv; x0.y *= iv; x0.z *= iv; x0.w *= iv;
                x1.x *= iv; x1.y *= iv; x1.z *= iv; x1.w *= iv;
                x2.x *= iv; x2.y *= iv; x2.z *= iv; x2.w *= iv;
                x3.x *= iv; x3.y *= iv; x3.z *= iv; x3.w *= iv;
                arow[ci]       = x0;
                arow[ci + 128] = x1;
                arow[ci + 256] = x2;
                arow[ci + 384] = x3;
            }
        }
    }
}

extern "C" void kernel_launch(void* const* d_in, const int* in_sizes, int n_in,
                              void* d_out, int out_size)
{
    const float* q    = (const float*)d_in[0];
    const float* k    = (const float*)d_in[1];
    const float* v    = (const float*)d_in[2];
    const float* cov  = (const float*)d_in[3];
    const float* lam  = (const float*)d_in[4];
    const int*   mask = (const int*)d_in[5];

    float* out  = (float*)d_out;                          // [B,H,S,D]
    float* attn = out + (size_t)Bq * Hq * Sq * Dq;        // [B,H,S,S]

    // pass 0: fold mask into cov (streaming, ~14 us)
    const size_t n4 = (size_t)Bq * Sq * Sq / 4;
    covmask_kernel<<<(unsigned)(n4 / 256), 256>>>(cov, mask);

    cudaFuncSetAttribute(attn_mma_kernel,
                         cudaFuncAttributeMaxDynamicSharedMemorySize, SMEM_BYTES);
    dim3 grid(Hq, Sq / BM / 2, Bq);  // (8, 8, 2) = 128 CTAs, single wave
    attn_mma_kernel<<<grid, NT, SMEM_BYTES>>>(q, k, v, lam, out, attn);
}

// round 16
// speedup vs baseline: 1.1356x; 1.0030x over previous
#include <cuda_runtime.h>
#include <cstdint>

#define Bq 2
#define Hq 8
#define Sq 2048
#define Dq 64
#define TEMP 8.0f

#define BM 128
#define BN 64
#define NT 512
#define NTILES (Sq / BN)   // 32

// smem word offsets
#define W_Q   0                      // q tf32 [128][68]
#define W_K0  8704                   // k raw f32 [64][68] natural [t][d], buf 0
#define W_K1  13056                  // buf 1
#define W_VR0 17408                  // v raw f32 [64][68] natural [t][d], buf 0
#define W_VR1 21760                  // buf 1
#define W_E   26112                  // e tf32-rounded [128][76] ([row][t])
#define W_RS  35840                  // rowsum [4][128] floats
#define W_CV0 36352                  // cov tile f32 [128][72], buf 0
#define W_CV1 45568                  // buf 1
#define SMEM_WORDS 54784
#define SMEM_BYTES (SMEM_WORDS * 4)  // 219136 B -> 1 CTA/SM

#define KVS 68     // K / Vraw row stride (words)
#define ES  76     // E row stride (words)
#define CVS 72     // cov tile row stride (words)

// masked-cov scratch: covm = mask ? cov : -3e4   (33.5 MB)
__device__ float g_covm[(size_t)Bq * Sq * Sq];

static __device__ __forceinline__ uint32_t f2tf32(float f) {
    uint32_t r;
    asm("cvt.rna.tf32.f32 %0, %1;" : "=r"(r) : "f"(f));
    return r;
}
// exp(x) on fma/alu pipes only (no MUFU). Caller clamps x >= -60.
static __device__ __forceinline__ float fexp(float x) {
    const float L2E = 1.4426950408889634f;
    float t = fmaf(x, L2E, 12582912.0f);          // 1.5*2^23: rounds to int
    int   in = __float_as_int(t);
    float n  = t - 12582912.0f;
    float z  = fmaf(x, L2E, -n);                  // frac in [-0.5, 0.5]
    float w  = z * 0.6931471805599453f;
    float p  = fmaf(w, 4.1666667e-2f, 0.16666667f);   // degree-4
    p = fmaf(p, w, 0.5f);
    p = fmaf(p, w, 1.0f);
    p = fmaf(p, w, 1.0f);
    return __int_as_float(__float_as_int(p) + (in << 23));
}
static __device__ __forceinline__ void mma_tf32(float* d, const uint32_t* a,
                                                const uint32_t* b) {
    asm volatile(
        "mma.sync.aligned.m16n8k8.row.col.f32.tf32.tf32.f32 "
        "{%0,%1,%2,%3}, {%4,%5,%6,%7}, {%8,%9}, {%0,%1,%2,%3};"
        : "+f"(d[0]), "+f"(d[1]), "+f"(d[2]), "+f"(d[3])
        : "r"(a[0]), "r"(a[1]), "r"(a[2]), "r"(a[3]), "r"(b[0]), "r"(b[1]));
}
static __device__ __forceinline__ void cp16(uint32_t dst, const void* src) {
    asm volatile("cp.async.cg.shared.global [%0], [%1], 16;"
                 :: "r"(dst), "l"(src) : "memory");
}
static __device__ __forceinline__ void bar_group(int id) {
    asm volatile("bar.sync %0, 128;" :: "r"(id) : "memory");
}

// Pre-kernel: fold mask into cov (one streaming pass, high occupancy)
__global__ __launch_bounds__(256, 8)
void covmask_kernel(const float* __restrict__ cov, const int* __restrict__ mask)
{
    size_t i = ((size_t)blockIdx.x * 256 + threadIdx.x) * 4;
    float4 c = *(const float4*)(cov + i);
    int4   m = *(const int4*)(mask + i);
    float4 o;
    o.x = m.x ? c.x : -30000.0f;
    o.y = m.y ? c.y : -30000.0f;
    o.z = m.z ? c.z : -30000.0f;
    o.w = m.w ? c.w : -30000.0f;
    *(float4*)(g_covm + i) = o;
}

__global__ __launch_bounds__(NT, 1)
void attn_mma_kernel(const float* __restrict__ q,
                     const float* __restrict__ k,
                     const float* __restrict__ v,
                     const float* __restrict__ lambda_w,
                     float* __restrict__ out,      // [B,H,S,D]
                     float* __restrict__ attn)     // [B,H,S,S]
{
    extern __shared__ uint32_t sw[];
    const uint32_t sbase = (uint32_t)__cvta_generic_to_shared(sw);
    uint32_t* QW  = sw + W_Q;
    uint32_t* EW  = sw + W_E;
    float*    EWf = (float*)(sw + W_E);
    float*    rs  = (float*)(sw + W_RS);

    const int h     = blockIdx.x;   // innermost -> heads share covm in L2
    const int mpair = blockIdx.y;   // 2 mtiles per CTA
    const int b     = blockIdx.z;
    const int bh    = b * Hq + h;
    const int tid   = threadIdx.x;
    const int wid   = tid >> 5;
    const int lane  = tid & 31;
    const int lg    = lane >> 2;    // group 0..7
    const int lt    = lane & 3;     // 0..3

    const int warp_m = wid & 3;     // row group (32 rows)
    const int warp_n = wid >> 2;    // 0..3: 16-col / 16-d slice
    const int rm = warp_m * 32;
    const int cn = warp_n * 16;
    const int dn = warp_n * 16;
    const int gtid = warp_n * 32 + lane;   // 0..127 within row-group

    const float lam  = lambda_w[h];
    const float wcov = lam / (lam + 1.0f);
    const float sqk  = 1.0f / ((lam + 1.0f) * TEMP);

    const float* kg = k + (size_t)bh * Sq * Dq;
    const float* vg = v + (size_t)bh * Sq * Dq;

    for (int m = 0; m < 2; m++) {
        const int mtile = mpair * 2 + m;
        const float* qg    = q + ((size_t)bh * Sq + (size_t)mtile * BM) * Dq;
        const float* covg  = g_covm + ((size_t)b * Sq + (size_t)mtile * BM) * Sq;
        float*       attng = attn + ((size_t)bh * Sq + (size_t)mtile * BM) * Sq;
        float*       outg  = out  + ((size_t)bh * Sq + (size_t)mtile * BM) * Dq;

        __syncthreads();   // previous mtile fully done (all smem free)

        // ---- prefetch tile 0 (K + Vraw + cov) ----
        {
#pragma unroll
            for (int it = 0; it < 2; it++) {
                int idx = tid + it * NT;   // 1024 16B segs each
                int t   = idx >> 4;
                int seg = idx & 15;
                cp16(sbase + (uint32_t)(W_K0  + t * KVS + seg * 4) * 4,
                     kg + (size_t)t * Dq + seg * 4);
                cp16(sbase + (uint32_t)(W_VR0 + t * KVS + seg * 4) * 4,
                     vg + (size_t)t * Dq + seg * 4);
            }
#pragma unroll
            for (int it = 0; it < 4; it++) {
                int idx = tid + it * NT;   // 2048 segs: 128 rows x 16 segs
                int r   = idx >> 4;
                int seg = idx & 15;
                cp16(sbase + (uint32_t)(W_CV0 + r * CVS + seg * 4) * 4,
                     covg + (size_t)r * Sq + seg * 4);
            }
            asm volatile("cp.async.commit_group;" ::: "memory");
        }

        // ---- fill q smem (tf32) ----
#pragma unroll
        for (int it = 0; it < 4; it++) {
            int idx = tid + it * NT;        // 2048 float4
            int r  = idx >> 4;
            int c4 = (idx & 15) << 2;
            float4 f = *(const float4*)&qg[r * Dq + c4];
            uint4 o;
            o.x = f2tf32(f.x); o.y = f2tf32(f.y);
            o.z = f2tf32(f.z); o.w = f2tf32(f.w);
            *(uint4*)&QW[r * 68 + c4] = o;
        }

        float oacc[2][2][4];
#pragma unroll
        for (int mi = 0; mi < 2; mi++)
#pragma unroll
            for (int nf = 0; nf < 2; nf++)
#pragma unroll
                for (int c = 0; c < 4; c++) oacc[mi][nf][c] = 0.0f;
        float rowsum[4] = {0.0f, 0.0f, 0.0f, 0.0f};

        for (int nt = 0; nt < NTILES; nt++) {
            const int buf = nt & 1;
            const int kof  = buf ? W_K1  : W_K0;
            const int vof  = buf ? W_VR1 : W_VR0;
            const int cvof = buf ? W_CV1 : W_CV0;
            const int t0  = nt * BN;

            // wait for current tile; full barrier also proves all groups are
            // done with the buffers we overwrite (prefetch + EW reuse).
            asm volatile("cp.async.wait_group 0;" ::: "memory");
            __syncthreads();

            // ---- prefetch next tile (K + V + cov) ----
            if (nt + 1 < NTILES) {
                const int kofn  = buf ? W_K0  : W_K1;
                const int vofn  = buf ? W_VR0 : W_VR1;
                const int cvofn = buf ? W_CV0 : W_CV1;
                const float* kn = kg + (size_t)(t0 + BN) * Dq;
                const float* vn = vg + (size_t)(t0 + BN) * Dq;
                const float* cvn = covg + t0 + BN;
#pragma unroll
                for (int it = 0; it < 2; it++) {
                    int idx = tid + it * NT;
                    int t   = idx >> 4;
                    int seg = idx & 15;
                    cp16(sbase + (uint32_t)(kofn + t * KVS + seg * 4) * 4,
                         kn + (size_t)t * Dq + seg * 4);
                    cp16(sbase + (uint32_t)(vofn + t * KVS + seg * 4) * 4,
                         vn + (size_t)t * Dq + seg * 4);
                }
#pragma unroll
                for (int it = 0; it < 4; it++) {
                    int idx = tid + it * NT;
                    int r   = idx >> 4;
                    int seg = idx & 15;
                    cp16(sbase + (uint32_t)(cvofn + r * CVS + seg * 4) * 4,
                         cvn + (size_t)r * Sq + seg * 4);
                }
                asm volatile("cp.async.commit_group;" ::: "memory");
            }

            // ---- scores: warp tile 32 rows x 16 cols, tf32 mma ----
            const uint32_t* KB = sw + kof;   // natural [t][d], raw f32 as tf32
            float acc[2][2][4];
#pragma unroll
            for (int mi = 0; mi < 2; mi++)
#pragma unroll
                for (int ni = 0; ni < 2; ni++)
#pragma unroll
                    for (int c = 0; c < 4; c++) acc[mi][ni][c] = 0.0f;

#pragma unroll
            for (int ks = 0; ks < 8; ks++) {
                const int kd = ks * 8;
                uint32_t a[2][4], bb[2][2];
#pragma unroll
                for (int mi = 0; mi < 2; mi++) {
                    const uint32_t* q0 = QW + (rm + mi * 16 + lg) * 68 + kd + lt;
                    a[mi][0] = q0[0];
                    a[mi][1] = q0[8 * 68];
                    a[mi][2] = q0[4];
                    a[mi][3] = q0[8 * 68 + 4];
                }
#pragma unroll
                for (int ni = 0; ni < 2; ni++) {
                    const uint32_t* kp = KB + (cn + ni * 8 + lg) * KVS + kd + lt;
                    bb[ni][0] = kp[0];
                    bb[ni][1] = kp[4];
                }
#pragma unroll
                for (int mi = 0; mi < 2; mi++)
#pragma unroll
                    for (int ni = 0; ni < 2; ni++)
                        mma_tf32(acc[mi][ni], a[mi], bb[ni]);
            }

            // ---- epilogue: blend (cov from smem), exp, e -> EW ----
            const float* CVf = (const float*)(sw + cvof);
#pragma unroll
            for (int mi = 0; mi < 2; mi++) {
#pragma unroll
                for (int rh = 0; rh < 2; rh++) {
                    const int r = rm + mi * 16 + lg + rh * 8;
                    float rsacc = 0.0f;
#pragma unroll
                    for (int ni = 0; ni < 2; ni++) {
                        const int c = cn + ni * 8 + 2 * lt;
                        float2 cvv = *(const float2*)&CVf[r * CVS + c];
                        float s0 = acc[mi][ni][rh * 2 + 0];
                        float s1 = acc[mi][ni][rh * 2 + 1];
                        float l0 = fmaxf(fmaf(sqk, s0, wcov * cvv.x), -60.0f);
                        float l1 = fmaxf(fmaf(sqk, s1, wcov * cvv.y), -60.0f);
                        uint32_t u0 = f2tf32(fexp(l0));
                        uint32_t u1 = f2tf32(fexp(l1));
                        rsacc += __uint_as_float(u0) + __uint_as_float(u1);
                        *(uint2*)&EW[r * ES + c] = make_uint2(u0, u1);
                    }
                    rowsum[mi * 2 + rh] += rsacc;
                }
            }
            // group-scoped barrier: only the 4 warps sharing warp_m must sync
            // (they alone produce/consume EW rows rm..rm+31)
            bar_group(1 + warp_m);

            // ---- attn store: this group's 32 rows, LDS.128 -> STG.128 ----
#pragma unroll
            for (int it = 0; it < 4; it++) {
                int idx = gtid + it * 128;      // 512 float4 in group
                int r   = rm + (idx >> 4);
                int c4  = (idx & 15) << 2;
                float4 e4 = *(const float4*)&EWf[r * ES + c4];
                *(float4*)&attng[(size_t)r * Sq + t0 + c4] = e4;
            }

            // ---- AV: warp tile 32 rows x 16 d, tf32 k8, k=64 in 8 steps ----
            const float* VRf = (const float*)(sw + vof);  // natural [t][d]
#pragma unroll
            for (int ks = 0; ks < 8; ks++) {
                const int tb = ks * 8;
                uint32_t a[2][4], bb[2][2];
#pragma unroll
                for (int mi = 0; mi < 2; mi++) {
                    const uint32_t* e0 = EW + (rm + mi * 16 + lg) * ES + tb + lt;
                    a[mi][0] = e0[0];
                    a[mi][1] = e0[8 * ES];
                    a[mi][2] = e0[4];
                    a[mi][3] = e0[8 * ES + 4];
                }
#pragma unroll
                for (int nf = 0; nf < 2; nf++) {
                    const float* vp = VRf + (tb + lt) * KVS + dn + nf * 8 + lg;
                    bb[nf][0] = f2tf32(vp[0]);
                    bb[nf][1] = f2tf32(vp[4 * KVS]);
                }
#pragma unroll
                for (int mi = 0; mi < 2; mi++)
#pragma unroll
                    for (int nf = 0; nf < 2; nf++)
                        mma_tf32(oacc[mi][nf], a[mi], bb[nf]);
            }
        }

        // ---- rowsum: reduce over lane&3, store partials ----
#pragma unroll
        for (int i = 0; i < 4; i++) {
            rowsum[i] += __shfl_xor_sync(0xffffffffu, rowsum[i], 1);
            rowsum[i] += __shfl_xor_sync(0xffffffffu, rowsum[i], 2);
        }
        __syncthreads();   // all EW/VR reads done before rs region reuse
        if (lt == 0) {
#pragma unroll
            for (int mi = 0; mi < 2; mi++)
#pragma unroll
                for (int rh = 0; rh < 2; rh++)
                    rs[warp_n * 128 + rm + mi * 16 + lg + rh * 8] = rowsum[mi * 2 + rh];
        }
        __syncthreads();

        // ---- write normalized output ----
#pragma unroll
        for (int mi = 0; mi < 2; mi++) {
#pragma unroll
            for (int rh = 0; rh < 2; rh++) {
                const int r = rm + mi * 16 + lg + rh * 8;
                const float iv = 1.0f /
                    (rs[r] + rs[128 + r] + rs[256 + r] + rs[384 + r]);
#pragma unroll
                for (int nf = 0; nf < 2; nf++) {
                    const int d = dn + nf * 8 + 2 * lt;
                    float2 o;
                    o.x = oacc[mi][nf][rh * 2 + 0] * iv;
                    o.y = oacc[mi][nf][rh * 2 + 1] * iv;
                    *(float2*)(outg + (size_t)r * Dq + d) = o;
                }
            }
        }

        // ---- fused normalize tail: scale this mtile's attn slice ----
        {
            const int rlane = tid >> 7;          // 0..3
            const int ci    = tid & 127;         // float4 col
#pragma unroll 2
            for (int rb = 0; rb < 32; rb++) {
                const int r = rb * 4 + rlane;
                const float iv = 1.0f /
                    (rs[r] + rs[128 + r] + rs[256 + r] + rs[384 + r]);
                float4* arow = (float4*)(attng + (size_t)r * Sq);
                float4 x0 = arow[ci];
                float4 x1 = arow[ci + 128];
                float4 x2 = arow[ci + 256];
                float4 x3 = arow[ci + 384];
                x0.x *= iv; x0.y *= iv; x0.z *= iv; x0.w *= iv;
                x1.x *= iv; x1.y *= iv; x1.z *= iv; x1.w *= iv;
                x2.x *= iv; x2.y *= iv; x2.z *= iv; x2.w *= iv;
                x3.x *= iv; x3.y *= iv; x3.z *= iv; x3.w *= iv;
                arow[ci]       = x0;
                arow[ci + 128] = x1;
                arow[ci + 256] = x2;
                arow[ci + 384] = x3;
            }
        }
    }
}

extern "C" void kernel_launch(void* const* d_in, const int* in_sizes, int n_in,
                              void* d_out, int out_size)
{
    const float* q    = (const float*)d_in[0];
    const float* k    = (const float*)d_in[1];
    const float* v    = (const float*)d_in[2];
    const float* cov  = (const float*)d_in[3];
    const float* lam  = (const float*)d_in[4];
    const int*   mask = (const int*)d_in[5];

    float* out  = (float*)d_out;                          // [B,H,S,D]
    float* attn = out + (size_t)Bq * Hq * Sq * Dq;        // [B,H,S,S]

    // pass 0: fold mask into cov (streaming, ~14 us)
    const size_t n4 = (size_t)Bq * Sq * Sq / 4;
    covmask_kernel<<<(unsigned)(n4 / 256), 256>>>(cov, mask);

    cudaFuncSetAttribute(attn_mma_kernel,
                         cudaFuncAttributeMaxDynamicSharedMemorySize, SMEM_BYTES);
    dim3 grid(Hq, Sq / BM / 2, Bq);  // (8, 8, 2) = 128 CTAs, single wave
    attn_mma_kernel<<<grid, NT, SMEM_BYTES>>>(q, k, v, lam, out, attn);
}